// round 2
// baseline (speedup 1.0000x reference)
#include <cuda_runtime.h>
#include <cstdint>

// Problem dims
#define NIN   128
#define NHID  256
#define NDEC  512
#define NOUT  10
#define BATCH 32
#define NSET  4096

// Encoder tiling
#define TM        64                    // rows per CTA
#define NTHREADS  256                   // 8 warps
#define ASTRIDE   260                   // padded float stride, activation buffers (bank-conflict free A-frag LDS)
#define WSTRIDE   264                   // padded float stride, staged W rows (bank-conflict free B-frag LDS)
#define NTILES_ENC (BATCH * NSET / TM)  // 2048 CTAs

// Deterministic scratch for per-tile column sums (fully overwritten every launch)
__device__ float g_partial[NTILES_ENC * NHID];

// ---------------------------------------------------------------------------
// helpers
// ---------------------------------------------------------------------------
__device__ __forceinline__ uint32_t f2tf32(float f) {
    uint32_t u;
    asm("cvt.rna.tf32.f32 %0, %1;" : "=r"(u) : "f"(f));
    return u;
}
__device__ __forceinline__ float tf32r(float f) {       // round fp32 -> tf32 value (kept in fp32 container)
    return __uint_as_float(f2tf32(f));
}

// m16n8k8 tf32 MMA, row.col, fp32 accumulate (D == C)
__device__ __forceinline__ void mma8(float c[4], const uint32_t a[4], uint32_t b0, uint32_t b1) {
    asm volatile(
        "mma.sync.aligned.m16n8k8.row.col.f32.tf32.tf32.f32 "
        "{%0,%1,%2,%3},{%4,%5,%6,%7},{%8,%9},{%0,%1,%2,%3};\n"
        : "+f"(c[0]), "+f"(c[1]), "+f"(c[2]), "+f"(c[3])
        : "r"(a[0]), "r"(a[1]), "r"(a[2]), "r"(a[3]), "r"(b0), "r"(b1));
}

// Load one 8-row k-slice of W (8 x 256 fp32 = 2048 floats) into registers (coalesced)
__device__ __forceinline__ void stage_load(const float* __restrict__ W, int kk, float4 v[2], int tid) {
    const float4* p = reinterpret_cast<const float4*>(W + kk * NHID);
    v[0] = p[tid];
    v[1] = p[tid + 256];
}

// Split into tf32 hi/lo and store to the staged smem slice
__device__ __forceinline__ void stage_store(const float4 v[2], float* whi, float* wlo, int tid) {
#pragma unroll
    for (int i = 0; i < 2; i++) {
        int lin = (tid + 256 * i) * 4;
        int k   = lin >> 8;       // / 256 (row of the 8xNHID slice)
        int cc  = lin & 255;      // col
        float* ph = whi + k * WSTRIDE + cc;
        float* pl = wlo + k * WSTRIDE + cc;
        float xs[4] = {v[i].x, v[i].y, v[i].z, v[i].w};
#pragma unroll
        for (int j = 0; j < 4; j++) {
            float h = tf32r(xs[j]);
            float l = tf32r(xs[j] - h);   // residual, also tf32-rounded
            ph[j] = h;
            pl[j] = l;
        }
    }
}

// ---------------------------------------------------------------------------
// one fused linear+bias+relu layer: out[64 x 256] = relu(in[64 x K] @ W[K x 256] + b)
// Activations are tf32-rounded fp32 in smem. Weights get hi/lo tf32 split (2 MMAs).
// If final: produce per-column sums over the 64 rows instead of writing `out`.
// ---------------------------------------------------------------------------
__device__ __forceinline__ void do_layer(
    const float* __restrict__ in, const float* __restrict__ W, const float* __restrict__ bias,
    int K, float* out, bool final_,
    float* whi0, float* wlo0, float* whi1, float* wlo1,
    float* redscratch /*>= 2048 floats*/, float* colsum /*256 floats*/,
    int block)
{
    const int tid  = threadIdx.x;
    const int lane = tid & 31;
    const int wp   = tid >> 5;     // warp id: covers cols [wp*32, wp*32+32)
    const int g    = lane >> 2;    // group id 0..7
    const int t    = lane & 3;     // thread-in-group 0..3

    float c[4][4][4];              // [row-block 0..3][n-tile 0..3][frag]
#pragma unroll
    for (int rb = 0; rb < 4; rb++)
#pragma unroll
        for (int nt = 0; nt < 4; nt++)
#pragma unroll
            for (int i = 0; i < 4; i++) c[rb][nt][i] = 0.f;

    const int nk = K >> 3;

    // prologue: stage slice 0
    {
        float4 v[2];
        stage_load(W, 0, v, tid);
        stage_store(v, whi0, wlo0, tid);
    }
    __syncthreads();

    for (int ks = 0; ks < nk; ks++) {
        float* whi = (ks & 1) ? whi1 : whi0;
        float* wlo = (ks & 1) ? wlo1 : wlo0;
        const bool more = (ks + 1 < nk);
        float4 nv[2];
        if (more) stage_load(W, (ks + 1) * 8, nv, tid);

        const int kk = ks * 8;

        // A fragments (shared across all n-tiles); rows = rb*16 + {g, g+8}
        uint32_t a[4][4];
#pragma unroll
        for (int rb = 0; rb < 4; rb++) {
            const int r = rb * 16 + g;
            a[rb][0] = __float_as_uint(in[r * ASTRIDE + kk + t]);
            a[rb][1] = __float_as_uint(in[(r + 8) * ASTRIDE + kk + t]);
            a[rb][2] = __float_as_uint(in[r * ASTRIDE + kk + t + 4]);
            a[rb][3] = __float_as_uint(in[(r + 8) * ASTRIDE + kk + t + 4]);
        }

#pragma unroll
        for (int nt = 0; nt < 4; nt++) {
            const int col = wp * 32 + nt * 8 + g;
            const uint32_t bh0 = __float_as_uint(whi[t * WSTRIDE + col]);
            const uint32_t bh1 = __float_as_uint(whi[(t + 4) * WSTRIDE + col]);
            const uint32_t bl0 = __float_as_uint(wlo[t * WSTRIDE + col]);
            const uint32_t bl1 = __float_as_uint(wlo[(t + 4) * WSTRIDE + col]);
#pragma unroll
            for (int rb = 0; rb < 4; rb++) {
                mma8(c[rb][nt], a[rb], bh0, bh1);
                mma8(c[rb][nt], a[rb], bl0, bl1);
            }
        }

        if (more) {
            float* nwhi = (ks & 1) ? whi0 : whi1;
            float* nwlo = (ks & 1) ? wlo0 : wlo1;
            stage_store(nv, nwhi, nwlo, tid);
        }
        __syncthreads();
    }

    // epilogue
    if (!final_) {
#pragma unroll
        for (int rb = 0; rb < 4; rb++) {
            const int r = rb * 16 + g;
#pragma unroll
            for (int nt = 0; nt < 4; nt++) {
                const int col = wp * 32 + nt * 8 + 2 * t;
                const float bb0 = bias[col], bb1 = bias[col + 1];
                out[r * ASTRIDE + col]           = tf32r(fmaxf(c[rb][nt][0] + bb0, 0.f));
                out[r * ASTRIDE + col + 1]       = tf32r(fmaxf(c[rb][nt][1] + bb1, 0.f));
                out[(r + 8) * ASTRIDE + col]     = tf32r(fmaxf(c[rb][nt][2] + bb0, 0.f));
                out[(r + 8) * ASTRIDE + col + 1] = tf32r(fmaxf(c[rb][nt][3] + bb1, 0.f));
            }
        }
        __syncthreads();
    } else {
        // Deterministic per-column reduction over this CTA's 64 rows.
        // Each (col) has exactly 8 contributing lanes (g = 0..7); thread reduces its 8 rows first.
#pragma unroll
        for (int nt = 0; nt < 4; nt++) {
            const int col = wp * 32 + nt * 8 + 2 * t;
            const float bb0 = bias[col], bb1 = bias[col + 1];
            float s0 = 0.f, s1 = 0.f;
#pragma unroll
            for (int rb = 0; rb < 4; rb++) {
                s0 += fmaxf(c[rb][nt][0] + bb0, 0.f) + fmaxf(c[rb][nt][2] + bb0, 0.f);
                s1 += fmaxf(c[rb][nt][1] + bb1, 0.f) + fmaxf(c[rb][nt][3] + bb1, 0.f);
            }
            redscratch[col * 8 + g]       = s0;
            redscratch[(col + 1) * 8 + g] = s1;
        }
        __syncthreads();
        float s = 0.f;
#pragma unroll
        for (int i = 0; i < 8; i++) s += redscratch[tid * 8 + i];
        colsum[tid] = s;
        __syncthreads();
        g_partial[block * NHID + tid] = colsum[tid];
    }
}

// ---------------------------------------------------------------------------
// Encoder: 3 fused layers per 64-row tile, per-tile column sums out to g_partial
// ---------------------------------------------------------------------------
__global__ void __launch_bounds__(NTHREADS, 1)
encoder_kernel(const float* __restrict__ x,
               const float* __restrict__ W1, const float* __restrict__ b1,
               const float* __restrict__ W2, const float* __restrict__ b2,
               const float* __restrict__ W3, const float* __restrict__ b3)
{
    extern __shared__ float smem[];
    float* bufA   = smem;                         // 64 x 260
    float* bufB   = bufA + TM * ASTRIDE;          // 64 x 260
    float* whi0   = bufB + TM * ASTRIDE;          // 8 x 264
    float* wlo0   = whi0 + 8 * WSTRIDE;
    float* whi1   = wlo0 + 8 * WSTRIDE;
    float* wlo1   = whi1 + 8 * WSTRIDE;
    float* colsum = wlo1 + 8 * WSTRIDE;           // 256

    const int tid   = threadIdx.x;
    const int block = blockIdx.x;
    const int row0  = block * TM;

    // Stage x tile [64 x 128] into bufA (tf32-rounded), coalesced float4 loads
    const float4* xt = reinterpret_cast<const float4*>(x + (size_t)row0 * NIN);
#pragma unroll
    for (int i = tid; i < TM * NIN / 4; i += NTHREADS) {
        float4 v = xt[i];
        int lin = i * 4;
        int r   = lin >> 7;     // / 128
        int cc  = lin & 127;
        float* p = bufA + r * ASTRIDE + cc;
        p[0] = tf32r(v.x); p[1] = tf32r(v.y); p[2] = tf32r(v.z); p[3] = tf32r(v.w);
    }
    __syncthreads();

    do_layer(bufA, W1, b1, NIN,  bufB, false, whi0, wlo0, whi1, wlo1, bufB, colsum, block);
    do_layer(bufB, W2, b2, NHID, bufA, false, whi0, wlo0, whi1, wlo1, bufA, colsum, block);
    // final layer: input bufA, use bufB as the (now free) reduction scratch
    do_layer(bufA, W3, b3, NHID, nullptr, true, whi0, wlo0, whi1, wlo1, bufB, colsum, block);
}

// ---------------------------------------------------------------------------
// Decoder: reduce partials -> m, p = relu(m*m), 3 fp32 linear layers. 1 CTA / batch.
// ---------------------------------------------------------------------------
__global__ void __launch_bounds__(256, 1)
decoder_kernel(const float* __restrict__ D1, const float* __restrict__ c1,
               const float* __restrict__ D2, const float* __restrict__ c2,
               const float* __restrict__ D3, const float* __restrict__ c3,
               float* __restrict__ out)
{
    __shared__ float p[NHID];
    __shared__ float d1s[NDEC];
    __shared__ float d2s[NDEC];
    const int b   = blockIdx.x;
    const int tid = threadIdx.x;

    // deterministic reduction over the 64 tile-partials of this batch
    const int tiles_per_batch = NSET / TM;  // 64
    float s = 0.f;
    const float* base = g_partial + (size_t)(b * tiles_per_batch) * NHID + tid;
#pragma unroll 8
    for (int i = 0; i < tiles_per_batch; i++) s += base[(size_t)i * NHID];
    const float m = s * (1.0f / NSET);
    p[tid] = fmaxf(m * m, 0.f);
    __syncthreads();

    // d1 = relu(p @ D1 + c1)   [256 -> 512]
    for (int j = tid; j < NDEC; j += 256) {
        float a0 = 0.f, a1 = 0.f, a2 = 0.f, a3 = 0.f;
#pragma unroll 4
        for (int k = 0; k < NHID; k += 4) {
            a0 += p[k]     * D1[(k)     * NDEC + j];
            a1 += p[k + 1] * D1[(k + 1) * NDEC + j];
            a2 += p[k + 2] * D1[(k + 2) * NDEC + j];
            a3 += p[k + 3] * D1[(k + 3) * NDEC + j];
        }
        d1s[j] = fmaxf(c1[j] + ((a0 + a1) + (a2 + a3)), 0.f);
    }
    __syncthreads();

    // d2 = relu(d1 @ D2 + c2)  [512 -> 512]
    for (int j = tid; j < NDEC; j += 256) {
        float a0 = 0.f, a1 = 0.f, a2 = 0.f, a3 = 0.f;
#pragma unroll 4
        for (int k = 0; k < NDEC; k += 4) {
            a0 += d1s[k]     * D2[(k)     * NDEC + j];
            a1 += d1s[k + 1] * D2[(k + 1) * NDEC + j];
            a2 += d1s[k + 2] * D2[(k + 2) * NDEC + j];
            a3 += d1s[k + 3] * D2[(k + 3) * NDEC + j];
        }
        d2s[j] = fmaxf(c2[j] + ((a0 + a1) + (a2 + a3)), 0.f);
    }
    __syncthreads();

    // out = d2 @ D3 + c3       [512 -> 10]
    if (tid < NOUT) {
        float a0 = 0.f, a1 = 0.f;
#pragma unroll 8
        for (int k = 0; k < NDEC; k += 2) {
            a0 += d2s[k]     * D3[(k)     * NOUT + tid];
            a1 += d2s[k + 1] * D3[(k + 1) * NOUT + tid];
        }
        out[b * NOUT + tid] = c3[tid] + (a0 + a1);
    }
}

// ---------------------------------------------------------------------------
extern "C" void kernel_launch(void* const* d_in, const int* in_sizes, int n_in,
                              void* d_out, int out_size)
{
    (void)in_sizes; (void)n_in; (void)out_size;
    const float* x  = (const float*)d_in[0];
    const float* W1 = (const float*)d_in[1];
    const float* b1 = (const float*)d_in[2];
    const float* W2 = (const float*)d_in[3];
    const float* b2 = (const float*)d_in[4];
    const float* W3 = (const float*)d_in[5];
    const float* b3 = (const float*)d_in[6];
    const float* D1 = (const float*)d_in[7];
    const float* c1 = (const float*)d_in[8];
    const float* D2 = (const float*)d_in[9];
    const float* c2 = (const float*)d_in[10];
    const float* D3 = (const float*)d_in[11];
    const float* c3 = (const float*)d_in[12];

    const int smem_bytes = (2 * TM * ASTRIDE + 4 * 8 * WSTRIDE + 256) * (int)sizeof(float);
    cudaFuncSetAttribute(encoder_kernel, cudaFuncAttributeMaxDynamicSharedMemorySize, smem_bytes);

    encoder_kernel<<<NTILES_ENC, NTHREADS, smem_bytes>>>(x, W1, b1, W2, b2, W3, b3);
    decoder_kernel<<<BATCH, 256>>>(D1, c1, D2, c2, D3, c3, (float*)d_out);
}

// round 5
// speedup vs baseline: 2.7982x; 2.7982x over previous
#include <cuda_runtime.h>
#include <cuda_bf16.h>
#include <cstdint>

// ---------------------------------------------------------------------------
// Problem dims
// ---------------------------------------------------------------------------
#define NIN   128
#define NHID  256
#define NDEC  512
#define NOUT  10
#define BATCH 32
#define NSET  4096

#define TM       128                    // rows per encoder CTA
#define NTILES   (BATCH * NSET / TM)    // 1024
#define THREADS  256                    // 8 warps: 2 (rows) x 4 (cols)

// Weight image: k-chunks of 32, each chunk = hi(16KB) + lo(16KB) = 32KB, pre-swizzled
#define CHUNK_BYTES 32768
#define NCHUNKS     20                  // L1:4  L2:8  L3:8  (contiguous)
#define IMG_BYTES   (NCHUNKS * CHUNK_BYTES)

// SMEM layout (bytes)
#define SMEM_A     0                    // 128 rows x 512B (256 bf16), XOR-swizzled
#define SMEM_W     65536                // 2 slots x 32KB
#define SMEM_BIAS  131072               // 256 floats
#define SMEM_RED   132096               // 2 x 256 floats
#define SMEM_TOTAL 134144

// ---------------------------------------------------------------------------
// Device globals (static; fully rewritten every launch)
// ---------------------------------------------------------------------------
__device__ __align__(128) uint8_t g_wimg[IMG_BYTES];
__device__ float g_partial[NTILES * NHID];
__device__ float g_p[BATCH * NHID];
__device__ float g_d1[BATCH * NDEC];
__device__ float g_d2[BATCH * NDEC];

// ---------------------------------------------------------------------------
// PTX helpers (all baseline sm_80-era PTX: safe at compute_103 target)
// ---------------------------------------------------------------------------
__device__ __forceinline__ uint32_t smem_u32(const void* p) {
    uint32_t a;
    asm("{ .reg .u64 t; cvta.to.shared.u64 t, %1; cvt.u32.u64 %0, t; }" : "=r"(a) : "l"(p));
    return a;
}

__device__ __forceinline__ void ldsm4(uint32_t r[4], uint32_t addr) {
    asm volatile("ldmatrix.sync.aligned.m8n8.x4.shared.b16 {%0,%1,%2,%3}, [%4];"
        : "=r"(r[0]), "=r"(r[1]), "=r"(r[2]), "=r"(r[3]) : "r"(addr));
}

__device__ __forceinline__ void mma16(float c[4], const uint32_t a[4], uint32_t b0, uint32_t b1) {
    asm volatile(
        "mma.sync.aligned.m16n8k16.row.col.f32.bf16.bf16.f32 "
        "{%0,%1,%2,%3},{%4,%5,%6,%7},{%8,%9},{%0,%1,%2,%3};"
        : "+f"(c[0]), "+f"(c[1]), "+f"(c[2]), "+f"(c[3])
        : "r"(a[0]), "r"(a[1]), "r"(a[2]), "r"(a[3]), "r"(b0), "r"(b1));
}

#define CP16(dst, src) \
    asm volatile("cp.async.cg.shared.global [%0], [%1], 16;" :: "r"(dst), "l"(src))
#define CP_COMMIT() asm volatile("cp.async.commit_group;" ::: "memory")
#define CP_WAIT1()  asm volatile("cp.async.wait_group 1;"  ::: "memory")

// B-image swizzle: rows are 64B (32 bf16 k-values); mask must stay BELOW the
// row stride (bits 4-5 only), applied to the k-offset on both store and load.
__device__ __forceinline__ uint32_t bmask(int n) { return ((uint32_t)(n >> 1) & 3u) << 4; }

// ---------------------------------------------------------------------------
// Weight pre-convert (once per launch): fp32 W[K,256] -> swizzled bf16 hi/lo image
// Layout per chunk (k-slice of 32): n-major rows of 64B,
// byte offset = n*64 + (((k&31)*2) ^ bmask(n)). hi at +0, lo at +16384.
// ---------------------------------------------------------------------------
__global__ void __launch_bounds__(256)
convert_weights(const float* __restrict__ W1, const float* __restrict__ W2,
                const float* __restrict__ W3)
{
    int idx = blockIdx.x * 256 + threadIdx.x;      // 0 .. 163839
    const float* W; int base;
    if (idx < 32768)      { W = W1; base = 0; }
    else if (idx < 98304) { W = W2; base = 4  * CHUNK_BYTES; idx -= 32768; }
    else                  { W = W3; base = 12 * CHUNK_BYTES; idx -= 98304; }
    int k = idx >> 8, n = idx & 255;
    float w = W[k * 256 + n];
    __nv_bfloat16 h = __float2bfloat16(w);
    __nv_bfloat16 l = __float2bfloat16(w - __bfloat162float(h));
    uint32_t off = (uint32_t)(n * 64) + (((uint32_t)((k & 31) * 2)) ^ bmask(n));
    uint8_t* cb = g_wimg + base + (uint32_t)(k >> 5) * CHUNK_BYTES;
    *(__nv_bfloat16*)(cb + off)         = h;
    *(__nv_bfloat16*)(cb + 16384 + off) = l;
}

// ---------------------------------------------------------------------------
// Encoder: 3 fused layers per 128-row tile. bf16 HMMA, ldmatrix, cp.async pipe.
// ---------------------------------------------------------------------------
__global__ void __launch_bounds__(THREADS, 1)
encoder_kernel(const float* __restrict__ x,
               const float* __restrict__ b1, const float* __restrict__ b2,
               const float* __restrict__ b3)
{
    extern __shared__ char smem[];
    const uint32_t sb = smem_u32(smem);
    const int tid  = threadIdx.x;
    const int lane = tid & 31;
    const int wid  = tid >> 5;
    const int wm   = wid >> 2;          // 0..1  (row half)
    const int wn   = wid & 3;           // 0..3  (col quarter)
    float* bias_s = (float*)(smem + SMEM_BIAS);
    float* red    = (float*)(smem + SMEM_RED);

    // --- prologue: prefetch weight chunks 0 and 1 (overlaps x staging) ---
    {
        const uint8_t* s0 = g_wimg;
        const uint8_t* s1 = g_wimg + CHUNK_BYTES;
        uint32_t d0 = sb + SMEM_W;
        uint32_t d1 = sb + SMEM_W + CHUNK_BYTES;
#pragma unroll
        for (int i = 0; i < 8; i++) CP16(d0 + (tid + i * 256) * 16, s0 + (tid + i * 256) * 16);
        CP_COMMIT();
#pragma unroll
        for (int i = 0; i < 8; i++) CP16(d1 + (tid + i * 256) * 16, s1 + (tid + i * 256) * 16);
        CP_COMMIT();
    }

    // --- stage x tile [128 x 128] fp32 -> bf16 into swizzled A (512B rows) ---
    {
        const float4* xt = (const float4*)(x + (size_t)blockIdx.x * TM * NIN);
#pragma unroll
        for (int i = tid; i < TM * NIN / 4; i += THREADS) {
            float4 v = xt[i];
            int p = i * 4;
            int r = p >> 7, cc = p & 127;
            uint32_t off = ((uint32_t)(r * 512 + cc * 2)) ^ ((uint32_t)(r & 7) << 4);
            __nv_bfloat162 lo2 = __floats2bfloat162_rn(v.x, v.y);
            __nv_bfloat162 hi2 = __floats2bfloat162_rn(v.z, v.w);
            uint2 u;
            u.x = *reinterpret_cast<uint32_t*>(&lo2);
            u.y = *reinterpret_cast<uint32_t*>(&hi2);
            *(uint2*)(smem + SMEM_A + off) = u;
        }
    }

    // --- per-thread ldmatrix address precompute ---
    // A: lanes 0-15 -> rows, lanes>>4 -> k halves (16B)
    uint32_t a_base[4], a_xm[4];
    {
        int r0 = wm * 64 + (lane & 15);
#pragma unroll
        for (int mt = 0; mt < 4; mt++) {
            int r = r0 + mt * 16;
            a_base[mt] = sb + SMEM_A + (uint32_t)(r * 512);
            a_xm[mt]   = ((uint32_t)(r & 7)) << 4;
        }
    }
    const uint32_t a_h16 = (uint32_t)(lane >> 4) * 16;
    // B: lanes 0-7 n0..7 h0 | 8-15 n0..7 h1 | 16-23 n8..15 h0 | 24-31 n8..15 h1
    uint32_t b_off[4], b_xm[4];
    {
        int n0 = wn * 64 + (lane & 7) + ((lane >> 4) << 3);
#pragma unroll
        for (int q = 0; q < 4; q++) {
            int n = n0 + q * 16;
            b_off[q] = (uint32_t)(n * 64);
            b_xm[q]  = bmask(n);
        }
    }
    const uint32_t b_h16 = ((uint32_t)(lane >> 3) & 1) * 16;

    const float* biases[3] = { b1, b2, b3 };
    const int    ncs[3]    = { 4, 8, 8 };
    const int    gg = lane >> 2, t = lane & 3;

    int g = 0;   // global chunk index (image is contiguous across layers)
    for (int L = 0; L < 3; L++) {
        __syncthreads();                 // protect bias_s / A from previous epilogue
        bias_s[tid] = biases[L][tid];

        float c[4][8][4];
#pragma unroll
        for (int mt = 0; mt < 4; mt++)
#pragma unroll
            for (int nt = 0; nt < 8; nt++)
#pragma unroll
                for (int e = 0; e < 4; e++) c[mt][nt][e] = 0.f;

        const int nc = ncs[L];
        for (int lk = 0; lk < nc; lk++, g++) {
            CP_WAIT1();
            __syncthreads();             // chunk g resident; everyone past previous mma
            const uint32_t wslot = sb + SMEM_W + (uint32_t)(g & 1) * CHUNK_BYTES;

#pragma unroll
            for (int ks = 0; ks < 2; ks++) {
                uint32_t a[4][4];
                const uint32_t kkA = (uint32_t)(lk * 64 + ks * 32) + a_h16;
#pragma unroll
                for (int mt = 0; mt < 4; mt++)
                    ldsm4(a[mt], a_base[mt] + (kkA ^ a_xm[mt]));

                const uint32_t kkB = (uint32_t)(ks * 32) + b_h16;
#pragma unroll
                for (int q = 0; q < 4; q++) {
                    uint32_t bh[4], bl[4];
                    ldsm4(bh, wslot + b_off[q] + (kkB ^ b_xm[q]));
                    ldsm4(bl, wslot + 16384 + b_off[q] + (kkB ^ b_xm[q]));
#pragma unroll
                    for (int mt = 0; mt < 4; mt++) {
                        mma16(c[mt][2 * q],     a[mt], bh[0], bh[1]);
                        mma16(c[mt][2 * q + 1], a[mt], bh[2], bh[3]);
                        mma16(c[mt][2 * q],     a[mt], bl[0], bl[1]);
                        mma16(c[mt][2 * q + 1], a[mt], bl[2], bl[3]);
                    }
                }
            }

            __syncthreads();             // all warps done reading slot g&1
            if (g + 2 < NCHUNKS) {
                uint32_t dst = sb + SMEM_W + (uint32_t)(g & 1) * CHUNK_BYTES;
                const uint8_t* src = g_wimg + (size_t)(g + 2) * CHUNK_BYTES;
#pragma unroll
                for (int i = 0; i < 8; i++)
                    CP16(dst + (tid + i * 256) * 16, src + (tid + i * 256) * 16);
            }
            CP_COMMIT();                 // always commit (keeps wait_group bookkeeping exact)
        }

        if (L < 2) {
            // epilogue: bias + relu -> bf16, rewrite A in place
#pragma unroll
            for (int mt = 0; mt < 4; mt++) {
                const int r0 = wm * 64 + mt * 16 + gg;
                const int r1 = r0 + 8;
                const uint32_t x0 = ((uint32_t)(r0 & 7)) << 4;
                const uint32_t x1 = ((uint32_t)(r1 & 7)) << 4;
#pragma unroll
                for (int nt = 0; nt < 8; nt++) {
                    const int col = wn * 64 + nt * 8 + 2 * t;
                    const float bb0 = bias_s[col], bb1 = bias_s[col + 1];
                    __nv_bfloat162 p0 = __floats2bfloat162_rn(
                        fmaxf(c[mt][nt][0] + bb0, 0.f), fmaxf(c[mt][nt][1] + bb1, 0.f));
                    __nv_bfloat162 p1 = __floats2bfloat162_rn(
                        fmaxf(c[mt][nt][2] + bb0, 0.f), fmaxf(c[mt][nt][3] + bb1, 0.f));
                    uint32_t o0 = ((uint32_t)(r0 * 512 + col * 2)) ^ x0;
                    uint32_t o1 = ((uint32_t)(r1 * 512 + col * 2)) ^ x1;
                    *(uint32_t*)(smem + SMEM_A + o0) = *reinterpret_cast<uint32_t*>(&p0);
                    *(uint32_t*)(smem + SMEM_A + o1) = *reinterpret_cast<uint32_t*>(&p1);
                }
            }
            // ordering vs next layer's reads: layer-loop-top __syncthreads
        } else {
            // final: bias + relu + column sums over this CTA's 128 rows
#pragma unroll
            for (int nt = 0; nt < 8; nt++) {
                const int col = wn * 64 + nt * 8 + 2 * t;
                const float bb0 = bias_s[col], bb1 = bias_s[col + 1];
                float s0 = 0.f, s1 = 0.f;
#pragma unroll
                for (int mt = 0; mt < 4; mt++) {
                    s0 += fmaxf(c[mt][nt][0] + bb0, 0.f) + fmaxf(c[mt][nt][2] + bb0, 0.f);
                    s1 += fmaxf(c[mt][nt][1] + bb1, 0.f) + fmaxf(c[mt][nt][3] + bb1, 0.f);
                }
#pragma unroll
                for (int off = 16; off >= 4; off >>= 1) {
                    s0 += __shfl_down_sync(0xffffffffu, s0, off);
                    s1 += __shfl_down_sync(0xffffffffu, s1, off);
                }
                if (lane < 4) {          // lane == t here; holds full 64-row sums
                    red[wm * 256 + col]     = s0;
                    red[wm * 256 + col + 1] = s1;
                }
            }
            __syncthreads();
            g_partial[(size_t)blockIdx.x * NHID + tid] = red[tid] + red[256 + tid];
        }
    }
}

// ---------------------------------------------------------------------------
// Decoder stage kernels (exact fp32, well parallelized)
// ---------------------------------------------------------------------------
__global__ void __launch_bounds__(256)
k_p_kernel()
{
    const int b = blockIdx.x, tid = threadIdx.x;
    const int tiles = NSET / TM;   // 32
    float s = 0.f;
    const float* base = g_partial + (size_t)(b * tiles) * NHID + tid;
#pragma unroll 8
    for (int i = 0; i < tiles; i++) s += base[(size_t)i * NHID];
    const float m = s * (1.0f / NSET);
    g_p[b * NHID + tid] = fmaxf(m * m, 0.f);
}

__global__ void __launch_bounds__(128)
k_d1_kernel(const float* __restrict__ D1, const float* __restrict__ c1)
{
    __shared__ float ps[NHID];
    const int b = blockIdx.y, tid = threadIdx.x;
    ps[tid]       = g_p[b * NHID + tid];
    ps[tid + 128] = g_p[b * NHID + tid + 128];
    __syncthreads();
    const int j = blockIdx.x * 128 + tid;
    const float* w = D1 + j;
    float a0 = 0.f, a1 = 0.f, a2 = 0.f, a3 = 0.f;
#pragma unroll 8
    for (int k = 0; k < NHID; k += 4) {
        a0 += ps[k]     * w[(size_t)(k)     * NDEC];
        a1 += ps[k + 1] * w[(size_t)(k + 1) * NDEC];
        a2 += ps[k + 2] * w[(size_t)(k + 2) * NDEC];
        a3 += ps[k + 3] * w[(size_t)(k + 3) * NDEC];
    }
    g_d1[b * NDEC + j] = fmaxf(((a0 + a1) + (a2 + a3)) + c1[j], 0.f);
}

__global__ void __launch_bounds__(128)
k_d2_kernel(const float* __restrict__ D2, const float* __restrict__ c2)
{
    __shared__ float ds[NDEC];
    const int b = blockIdx.y, tid = threadIdx.x;
#pragma unroll
    for (int i = 0; i < 4; i++) ds[tid + i * 128] = g_d1[b * NDEC + tid + i * 128];
    __syncthreads();
    const int j = blockIdx.x * 128 + tid;
    const float* w = D2 + j;
    float a0 = 0.f, a1 = 0.f, a2 = 0.f, a3 = 0.f;
#pragma unroll 8
    for (int k = 0; k < NDEC; k += 4) {
        a0 += ds[k]     * w[(size_t)(k)     * NDEC];
        a1 += ds[k + 1] * w[(size_t)(k + 1) * NDEC];
        a2 += ds[k + 2] * w[(size_t)(k + 2) * NDEC];
        a3 += ds[k + 3] * w[(size_t)(k + 3) * NDEC];
    }
    g_d2[b * NDEC + j] = fmaxf(((a0 + a1) + (a2 + a3)) + c2[j], 0.f);
}

__global__ void __launch_bounds__(64)
k_d3_kernel(const float* __restrict__ D3, const float* __restrict__ c3, float* __restrict__ out)
{
    __shared__ float part[40];
    const int b = blockIdx.x, t = threadIdx.x;
    if (t < 40) {
        const int col = t >> 2, q = t & 3;
        const float* d2 = g_d2 + b * NDEC + q * 128;
        float a = 0.f;
#pragma unroll 16
        for (int k = 0; k < 128; k++) a += d2[k] * D3[(q * 128 + k) * NOUT + col];
        part[t] = a;
    }
    __syncthreads();
    if (t < NOUT)
        out[b * NOUT + t] = c3[t] +
            ((part[4 * t] + part[4 * t + 1]) + (part[4 * t + 2] + part[4 * t + 3]));
}

// ---------------------------------------------------------------------------
extern "C" void kernel_launch(void* const* d_in, const int* in_sizes, int n_in,
                              void* d_out, int out_size)
{
    (void)in_sizes; (void)n_in; (void)out_size;
    const float* x  = (const float*)d_in[0];
    const float* W1 = (const float*)d_in[1];
    const float* b1 = (const float*)d_in[2];
    const float* W2 = (const float*)d_in[3];
    const float* b2 = (const float*)d_in[4];
    const float* W3 = (const float*)d_in[5];
    const float* b3 = (const float*)d_in[6];
    const float* D1 = (const float*)d_in[7];
    const float* c1 = (const float*)d_in[8];
    const float* D2 = (const float*)d_in[9];
    const float* c2 = (const float*)d_in[10];
    const float* D3 = (const float*)d_in[11];
    const float* c3 = (const float*)d_in[12];

    cudaFuncSetAttribute(encoder_kernel, cudaFuncAttributeMaxDynamicSharedMemorySize, SMEM_TOTAL);

    convert_weights<<<640, 256>>>(W1, W2, W3);
    encoder_kernel<<<NTILES, THREADS, SMEM_TOTAL>>>(x, b1, b2, b3);
    k_p_kernel<<<BATCH, 256>>>();
    {
        dim3 gdim(4, BATCH);
        k_d1_kernel<<<gdim, 128>>>(D1, c1);
        k_d2_kernel<<<gdim, 128>>>(D2, c2);
    }
    k_d3_kernel<<<BATCH, 64>>>(D3, c3, (float*)d_out);
}

// round 6
// speedup vs baseline: 2.9045x; 1.0380x over previous
#include <cuda_runtime.h>
#include <cuda_bf16.h>
#include <cstdint>

// ---------------------------------------------------------------------------
// Problem dims
// ---------------------------------------------------------------------------
#define NIN   128
#define NHID  256
#define NDEC  512
#define NOUT  10
#define BATCH 32
#define NSET  4096

#define TM       128                    // rows per encoder CTA
#define NTILES   (BATCH * NSET / TM)    // 1024
#define THREADS  512                    // 16 warps: 4 (rows) x 4 (cols)

// Weight image: k-chunks of 32, each chunk = hi(16KB) + lo(16KB) = 32KB, pre-swizzled
#define CHUNK_BYTES 32768
#define NCHUNKS     20                  // L1:4  L2:8  L3:8  (contiguous)
#define IMG_BYTES   (NCHUNKS * CHUNK_BYTES)
#define NSLOTS      4                   // cp.async ring depth

// SMEM layout (bytes)
#define SMEM_A     0                    // 128 rows x 512B (256 bf16), XOR-swizzled
#define SMEM_W     65536                // 4 slots x 32KB
#define SMEM_BIAS  196608               // 256 floats
#define SMEM_RED   197632               // 4 x 256 floats
#define SMEM_TOTAL 201728

// ---------------------------------------------------------------------------
// Device globals (static; fully rewritten every launch)
// ---------------------------------------------------------------------------
__device__ __align__(128) uint8_t g_wimg[IMG_BYTES];
__device__ float g_partial[NTILES * NHID];

// ---------------------------------------------------------------------------
// PTX helpers (baseline sm_80-era PTX only: safe at compute_103 target)
// ---------------------------------------------------------------------------
__device__ __forceinline__ uint32_t smem_u32(const void* p) {
    uint32_t a;
    asm("{ .reg .u64 t; cvta.to.shared.u64 t, %1; cvt.u32.u64 %0, t; }" : "=r"(a) : "l"(p));
    return a;
}

__device__ __forceinline__ void ldsm4(uint32_t r[4], uint32_t addr) {
    asm volatile("ldmatrix.sync.aligned.m8n8.x4.shared.b16 {%0,%1,%2,%3}, [%4];"
        : "=r"(r[0]), "=r"(r[1]), "=r"(r[2]), "=r"(r[3]) : "r"(addr));
}

__device__ __forceinline__ void mma16(float c[4], const uint32_t a[4], uint32_t b0, uint32_t b1) {
    asm volatile(
        "mma.sync.aligned.m16n8k16.row.col.f32.bf16.bf16.f32 "
        "{%0,%1,%2,%3},{%4,%5,%6,%7},{%8,%9},{%0,%1,%2,%3};"
        : "+f"(c[0]), "+f"(c[1]), "+f"(c[2]), "+f"(c[3])
        : "r"(a[0]), "r"(a[1]), "r"(a[2]), "r"(a[3]), "r"(b0), "r"(b1));
}

#define CP16(dst, src) \
    asm volatile("cp.async.cg.shared.global [%0], [%1], 16;" :: "r"(dst), "l"(src))
#define CP_COMMIT() asm volatile("cp.async.commit_group;" ::: "memory")
#define CP_WAIT2()  asm volatile("cp.async.wait_group 2;"  ::: "memory")

// B-image swizzle: rows are 64B (32 bf16 k-values); mask stays below the row
// stride (bits 4-5 only), applied to the k-offset on both store and load.
__device__ __forceinline__ uint32_t bmask(int n) { return ((uint32_t)(n >> 1) & 3u) << 4; }

// ---------------------------------------------------------------------------
// Weight pre-convert (once per launch): fp32 W[K,256] -> swizzled bf16 hi/lo image
// ---------------------------------------------------------------------------
__global__ void __launch_bounds__(256)
convert_weights(const float* __restrict__ W1, const float* __restrict__ W2,
                const float* __restrict__ W3)
{
    int idx = blockIdx.x * 256 + threadIdx.x;      // 0 .. 163839
    const float* W; int base;
    if (idx < 32768)      { W = W1; base = 0; }
    else if (idx < 98304) { W = W2; base = 4  * CHUNK_BYTES; idx -= 32768; }
    else                  { W = W3; base = 12 * CHUNK_BYTES; idx -= 98304; }
    int k = idx >> 8, n = idx & 255;
    float w = W[k * 256 + n];
    __nv_bfloat16 h = __float2bfloat16(w);
    __nv_bfloat16 l = __float2bfloat16(w - __bfloat162float(h));
    uint32_t off = (uint32_t)(n * 64) + (((uint32_t)((k & 31) * 2)) ^ bmask(n));
    uint8_t* cb = g_wimg + base + (uint32_t)(k >> 5) * CHUNK_BYTES;
    *(__nv_bfloat16*)(cb + off)         = h;
    *(__nv_bfloat16*)(cb + 16384 + off) = l;
}

// ---------------------------------------------------------------------------
// Encoder: 3 fused layers per 128-row tile. bf16 HMMA, ldmatrix, 4-slot cp.async.
// 16 warps: wm = wid>>2 (row group of 32), wn = wid&3 (col group of 64).
// ---------------------------------------------------------------------------
__global__ void __launch_bounds__(THREADS, 1)
encoder_kernel(const float* __restrict__ x,
               const float* __restrict__ b1, const float* __restrict__ b2,
               const float* __restrict__ b3)
{
    extern __shared__ char smem[];
    const uint32_t sb = smem_u32(smem);
    const int tid  = threadIdx.x;
    const int lane = tid & 31;
    const int wid  = tid >> 5;
    const int wm   = wid >> 2;          // 0..3  (row group, 32 rows)
    const int wn   = wid & 3;           // 0..3  (col group, 64 cols)
    float* bias_s = (float*)(smem + SMEM_BIAS);
    float* red    = (float*)(smem + SMEM_RED);

    // --- prologue: prefetch weight chunks 0,1,2 (overlaps x staging) ---
#pragma unroll
    for (int c0 = 0; c0 < 3; c0++) {
        const uint8_t* src = g_wimg + (size_t)c0 * CHUNK_BYTES;
        uint32_t dst = sb + SMEM_W + (uint32_t)c0 * CHUNK_BYTES;
#pragma unroll
        for (int i = 0; i < 4; i++)
            CP16(dst + (tid + i * 512) * 16, src + (tid + i * 512) * 16);
        CP_COMMIT();
    }

    // --- stage x tile [128 x 128] fp32 -> bf16 into swizzled A (512B rows) ---
    {
        const float4* xt = (const float4*)(x + (size_t)blockIdx.x * TM * NIN);
#pragma unroll
        for (int i = tid; i < TM * NIN / 4; i += THREADS) {
            float4 v = xt[i];
            int p = i * 4;
            int r = p >> 7, cc = p & 127;
            uint32_t off = ((uint32_t)(r * 512 + cc * 2)) ^ ((uint32_t)(r & 7) << 4);
            __nv_bfloat162 lo2 = __floats2bfloat162_rn(v.x, v.y);
            __nv_bfloat162 hi2 = __floats2bfloat162_rn(v.z, v.w);
            uint2 u;
            u.x = *reinterpret_cast<uint32_t*>(&lo2);
            u.y = *reinterpret_cast<uint32_t*>(&hi2);
            *(uint2*)(smem + SMEM_A + off) = u;
        }
    }

    // --- per-thread ldmatrix address precompute ---
    uint32_t a_base[2], a_xm[2];
    {
        int r0 = wm * 32 + (lane & 15);
#pragma unroll
        for (int mt = 0; mt < 2; mt++) {
            int r = r0 + mt * 16;
            a_base[mt] = sb + SMEM_A + (uint32_t)(r * 512);
            a_xm[mt]   = ((uint32_t)(r & 7)) << 4;
        }
    }
    const uint32_t a_h16 = (uint32_t)(lane >> 4) * 16;
    uint32_t b_off[4], b_xm[4];
    {
        int n0 = wn * 64 + (lane & 7) + ((lane >> 4) << 3);
#pragma unroll
        for (int q = 0; q < 4; q++) {
            int n = n0 + q * 16;
            b_off[q] = (uint32_t)(n * 64);
            b_xm[q]  = bmask(n);
        }
    }
    const uint32_t b_h16 = ((uint32_t)(lane >> 3) & 1) * 16;

    const float* biases[3] = { b1, b2, b3 };
    const int    ncs[3]    = { 4, 8, 8 };
    const int    gg = lane >> 2, t = lane & 3;

    __syncthreads();                     // x staging done (covers first mma)

    int g = 0;   // global chunk index (image contiguous across layers)
    for (int L = 0; L < 3; L++) {
        if (tid < 256) bias_s[tid] = biases[L][tid];

        float c[2][8][4];
#pragma unroll
        for (int mt = 0; mt < 2; mt++)
#pragma unroll
            for (int nt = 0; nt < 8; nt++)
#pragma unroll
                for (int e = 0; e < 4; e++) c[mt][nt][e] = 0.f;

        const int nc = ncs[L];
        for (int lk = 0; lk < nc; lk++, g++) {
            CP_WAIT2();                  // chunk g resident (pending: g+1,g+2)
            __syncthreads();             // everyone past chunk g-1 reads; slot (g+3)%4 free

            if (g + 3 < NCHUNKS) {       // refill the slot read two chunks ago
                uint32_t dst = sb + SMEM_W + (uint32_t)((g + 3) & 3) * CHUNK_BYTES;
                const uint8_t* src = g_wimg + (size_t)(g + 3) * CHUNK_BYTES;
#pragma unroll
                for (int i = 0; i < 4; i++)
                    CP16(dst + (tid + i * 512) * 16, src + (tid + i * 512) * 16);
            }
            CP_COMMIT();                 // always commit (exact wait_group bookkeeping)

            const uint32_t wslot = sb + SMEM_W + (uint32_t)(g & 3) * CHUNK_BYTES;
#pragma unroll
            for (int ks = 0; ks < 2; ks++) {
                uint32_t a[2][4];
                const uint32_t kkA = (uint32_t)(lk * 64 + ks * 32) + a_h16;
#pragma unroll
                for (int mt = 0; mt < 2; mt++)
                    ldsm4(a[mt], a_base[mt] + (kkA ^ a_xm[mt]));

                const uint32_t kkB = (uint32_t)(ks * 32) + b_h16;
#pragma unroll
                for (int q = 0; q < 4; q++) {
                    uint32_t bh[4], bl[4];
                    ldsm4(bh, wslot + b_off[q] + (kkB ^ b_xm[q]));
                    ldsm4(bl, wslot + 16384 + b_off[q] + (kkB ^ b_xm[q]));
#pragma unroll
                    for (int mt = 0; mt < 2; mt++) {
                        mma16(c[mt][2 * q],     a[mt], bh[0], bh[1]);
                        mma16(c[mt][2 * q + 1], a[mt], bh[2], bh[3]);
                        mma16(c[mt][2 * q],     a[mt], bl[0], bl[1]);
                        mma16(c[mt][2 * q + 1], a[mt], bl[2], bl[3]);
                    }
                }
            }
        }

        __syncthreads();                 // all mma reads of A done before epilogue writes

        if (L < 2) {
            // epilogue: bias + relu -> bf16, rewrite A in place
#pragma unroll
            for (int mt = 0; mt < 2; mt++) {
                const int r0 = wm * 32 + mt * 16 + gg;
                const int r1 = r0 + 8;
                const uint32_t x0 = ((uint32_t)(r0 & 7)) << 4;
                const uint32_t x1 = ((uint32_t)(r1 & 7)) << 4;
#pragma unroll
                for (int nt = 0; nt < 8; nt++) {
                    const int col = wn * 64 + nt * 8 + 2 * t;
                    const float bb0 = bias_s[col], bb1 = bias_s[col + 1];
                    __nv_bfloat162 p0 = __floats2bfloat162_rn(
                        fmaxf(c[mt][nt][0] + bb0, 0.f), fmaxf(c[mt][nt][1] + bb1, 0.f));
                    __nv_bfloat162 p1 = __floats2bfloat162_rn(
                        fmaxf(c[mt][nt][2] + bb0, 0.f), fmaxf(c[mt][nt][3] + bb1, 0.f));
                    uint32_t o0 = ((uint32_t)(r0 * 512 + col * 2)) ^ x0;
                    uint32_t o1 = ((uint32_t)(r1 * 512 + col * 2)) ^ x1;
                    *(uint32_t*)(smem + SMEM_A + o0) = *reinterpret_cast<uint32_t*>(&p0);
                    *(uint32_t*)(smem + SMEM_A + o1) = *reinterpret_cast<uint32_t*>(&p1);
                }
            }
            __syncthreads();             // epilogue done before next bias write / mma
        } else {
            // final: bias + relu + column sums over this CTA's 128 rows
#pragma unroll
            for (int nt = 0; nt < 8; nt++) {
                const int col = wn * 64 + nt * 8 + 2 * t;
                const float bb0 = bias_s[col], bb1 = bias_s[col + 1];
                float s0 = 0.f, s1 = 0.f;
#pragma unroll
                for (int mt = 0; mt < 2; mt++) {
                    s0 += fmaxf(c[mt][nt][0] + bb0, 0.f) + fmaxf(c[mt][nt][2] + bb0, 0.f);
                    s1 += fmaxf(c[mt][nt][1] + bb1, 0.f) + fmaxf(c[mt][nt][3] + bb1, 0.f);
                }
#pragma unroll
                for (int off = 16; off >= 4; off >>= 1) {
                    s0 += __shfl_down_sync(0xffffffffu, s0, off);
                    s1 += __shfl_down_sync(0xffffffffu, s1, off);
                }
                if (lane < 4) {          // lane == t; holds this warp's 32-row sums
                    red[wm * 256 + col]     = s0;
                    red[wm * 256 + col + 1] = s1;
                }
            }
            __syncthreads();
            if (tid < 256)
                g_partial[(size_t)blockIdx.x * NHID + tid] =
                    (red[tid] + red[256 + tid]) + (red[512 + tid] + red[768 + tid]);
        }
    }
}

// ---------------------------------------------------------------------------
// Fused decoder: mean->square->d1->d2->d3, one CTA per batch, 512 threads.
// All weight streams are k-outer, coalesced row-major. Exact fp32.
// ---------------------------------------------------------------------------
__global__ void __launch_bounds__(512, 1)
decoder_kernel(const float* __restrict__ D1, const float* __restrict__ c1,
               const float* __restrict__ D2, const float* __restrict__ c2,
               const float* __restrict__ D3, const float* __restrict__ c3,
               float* __restrict__ out)
{
    __shared__ float p_s[NHID];
    __shared__ float d1_s[NDEC];
    __shared__ float d2_s[NDEC];
    __shared__ float wred[16 * NOUT];
    const int b = blockIdx.x, tid = threadIdx.x;
    const int lane = tid & 31, wrp = tid >> 5;

    // mean over 32 tile-partials (deterministic fixed order), then p = relu(m*m)
    if (tid < NHID) {
        const int tiles = NSET / TM;     // 32
        float s = 0.f;
        const float* base = g_partial + (size_t)(b * tiles) * NHID + tid;
#pragma unroll 8
        for (int i = 0; i < tiles; i++) s += base[(size_t)i * NHID];
        const float m = s * (1.0f / NSET);
        p_s[tid] = fmaxf(m * m, 0.f);
    }
    __syncthreads();

    // d1 = relu(p @ D1 + c1): thread j owns output j; k-outer coalesced stream
    {
        float acc = 0.f;
        const float* w = D1 + tid;
#pragma unroll 8
        for (int k = 0; k < NHID; k++) acc += p_s[k] * w[(size_t)k * NDEC];
        d1_s[tid] = fmaxf(acc + c1[tid], 0.f);
    }
    __syncthreads();

    // d2 = relu(d1 @ D2 + c2)
    {
        float acc = 0.f;
        const float* w = D2 + tid;
#pragma unroll 8
        for (int k = 0; k < NDEC; k++) acc += d1_s[k] * w[(size_t)k * NDEC];
        d2_s[tid] = fmaxf(acc + c2[tid], 0.f);
    }
    __syncthreads();

    // d3: thread k contributes d2[k]*D3[k][:]; warp-shfl + smem tree reduce
    {
        float part[NOUT];
        const float v = d2_s[tid];
        const float* w = D3 + (size_t)tid * NOUT;
#pragma unroll
        for (int o = 0; o < NOUT; o++) part[o] = v * w[o];
#pragma unroll
        for (int off = 16; off >= 1; off >>= 1)
#pragma unroll
            for (int o = 0; o < NOUT; o++)
                part[o] += __shfl_down_sync(0xffffffffu, part[o], off);
        if (lane == 0)
#pragma unroll
            for (int o = 0; o < NOUT; o++) wred[wrp * NOUT + o] = part[o];
    }
    __syncthreads();
    if (tid < NOUT) {
        float s = 0.f;
#pragma unroll
        for (int w = 0; w < 16; w++) s += wred[w * NOUT + tid];
        out[b * NOUT + tid] = c3[tid] + s;
    }
}

// ---------------------------------------------------------------------------
extern "C" void kernel_launch(void* const* d_in, const int* in_sizes, int n_in,
                              void* d_out, int out_size)
{
    (void)in_sizes; (void)n_in; (void)out_size;
    const float* x  = (const float*)d_in[0];
    const float* W1 = (const float*)d_in[1];
    const float* b1 = (const float*)d_in[2];
    const float* W2 = (const float*)d_in[3];
    const float* b2 = (const float*)d_in[4];
    const float* W3 = (const float*)d_in[5];
    const float* b3 = (const float*)d_in[6];
    const float* D1 = (const float*)d_in[7];
    const float* c1 = (const float*)d_in[8];
    const float* D2 = (const float*)d_in[9];
    const float* c2 = (const float*)d_in[10];
    const float* D3 = (const float*)d_in[11];
    const float* c3 = (const float*)d_in[12];

    cudaFuncSetAttribute(encoder_kernel, cudaFuncAttributeMaxDynamicSharedMemorySize, SMEM_TOTAL);

    convert_weights<<<640, 256>>>(W1, W2, W3);
    encoder_kernel<<<NTILES, THREADS, SMEM_TOTAL>>>(x, b1, b2, b3);
    decoder_kernel<<<BATCH, 512>>>(D1, c1, D2, c2, D3, c3, (float*)d_out);
}

// round 7
// speedup vs baseline: 2.9592x; 1.0188x over previous
#include <cuda_runtime.h>
#include <cuda_bf16.h>
#include <cstdint>

// ---------------------------------------------------------------------------
// Problem dims
// ---------------------------------------------------------------------------
#define NIN   128
#define NHID  256
#define NDEC  512
#define NOUT  10
#define BATCH 32
#define NSET  4096

#define TM       128                    // rows per encoder CTA
#define NTILES   (BATCH * NSET / TM)    // 1024
#define THREADS  256                    // 8 warps: 2 (row halves) x 4 (col quarters)

// Weight image: k-chunks of 32, each chunk = hi(16KB) + lo(16KB) = 32KB, pre-swizzled
#define CHUNK_BYTES 32768
#define NCHUNKS     20                  // L1:4  L2:8  L3:8  (contiguous)
#define IMG_BYTES   (NCHUNKS * CHUNK_BYTES)

// SMEM layout (bytes)
#define SMEM_A     0                    // 128 rows x 512B (256 bf16), XOR-swizzled
#define SMEM_W     65536                // 4 slots x 32KB ring
#define SMEM_BIAS  196608               // 256 floats
#define SMEM_RED   197632               // 2 x 256 floats
#define SMEM_TOTAL 199680

// ---------------------------------------------------------------------------
// Device globals (static; fully rewritten every launch)
// ---------------------------------------------------------------------------
__device__ __align__(128) uint8_t g_wimg[IMG_BYTES];
__device__ float g_partial[NTILES * NHID];

// ---------------------------------------------------------------------------
// PTX helpers (baseline sm_80-era PTX only: safe at compute_103 target)
// ---------------------------------------------------------------------------
__device__ __forceinline__ uint32_t smem_u32(const void* p) {
    uint32_t a;
    asm("{ .reg .u64 t; cvta.to.shared.u64 t, %1; cvt.u32.u64 %0, t; }" : "=r"(a) : "l"(p));
    return a;
}

__device__ __forceinline__ void ldsm4(uint32_t r[4], uint32_t addr) {
    asm volatile("ldmatrix.sync.aligned.m8n8.x4.shared.b16 {%0,%1,%2,%3}, [%4];"
        : "=r"(r[0]), "=r"(r[1]), "=r"(r[2]), "=r"(r[3]) : "r"(addr));
}

__device__ __forceinline__ void mma16(float c[4], const uint32_t a[4], uint32_t b0, uint32_t b1) {
    asm volatile(
        "mma.sync.aligned.m16n8k16.row.col.f32.bf16.bf16.f32 "
        "{%0,%1,%2,%3},{%4,%5,%6,%7},{%8,%9},{%0,%1,%2,%3};"
        : "+f"(c[0]), "+f"(c[1]), "+f"(c[2]), "+f"(c[3])
        : "r"(a[0]), "r"(a[1]), "r"(a[2]), "r"(a[3]), "r"(b0), "r"(b1));
}

#define CP16(dst, src) \
    asm volatile("cp.async.cg.shared.global [%0], [%1], 16;" :: "r"(dst), "l"(src))
#define CP_COMMIT() asm volatile("cp.async.commit_group;" ::: "memory")
#define CP_WAIT2()  asm volatile("cp.async.wait_group 2;"  ::: "memory")

// B-image swizzle: rows are 64B (32 bf16 k-values); mask stays below the row
// stride (bits 4-5 only), applied to the k-offset on both store and load.
__device__ __forceinline__ uint32_t bmask(int n) { return ((uint32_t)(n >> 1) & 3u) << 4; }

// ---------------------------------------------------------------------------
// Weight pre-convert (once per launch): fp32 W[K,256] -> swizzled bf16 hi/lo image.
// One thread per packed uint32 slot; stores fully coalesced, reads gathered.
// ---------------------------------------------------------------------------
__global__ void __launch_bounds__(256)
convert_weights(const float* __restrict__ W1, const float* __restrict__ W2,
                const float* __restrict__ W3)
{
    int idx = blockIdx.x * 256 + threadIdx.x;    // 0 .. 81919 (uint32 slots)
    int chunk = idx >> 12;                       // 4096 slots per chunk
    int rem   = idx & 4095;
    int n     = rem >> 4;                        // 0..255
    int s     = rem & 15;                        // uint32 slot within 64B row

    const float* W; int kbase;
    if (chunk < 4)       { W = W1; kbase = chunk * 32; }
    else if (chunk < 12) { W = W2; kbase = (chunk - 4) * 32; }
    else                 { W = W3; kbase = (chunk - 12) * 32; }

    // inverse swizzle: stored byte = (k*2) ^ bm  =>  k*2 = (4s) ^ bm
    uint32_t bm = bmask(n);
    int k0 = (int)((((uint32_t)(4 * s)) ^ bm) >> 1);   // even; pair is (k0, k0+1)
    float w0 = W[(kbase + k0) * 256 + n];
    float w1 = W[(kbase + k0 + 1) * 256 + n];

    __nv_bfloat16 h0 = __float2bfloat16(w0);
    __nv_bfloat16 h1 = __float2bfloat16(w1);
    __nv_bfloat16 l0 = __float2bfloat16(w0 - __bfloat162float(h0));
    __nv_bfloat16 l1 = __float2bfloat16(w1 - __bfloat162float(h1));

    uint32_t hi = ((uint32_t)*reinterpret_cast<uint16_t*>(&h1) << 16) |
                   (uint32_t)*reinterpret_cast<uint16_t*>(&h0);
    uint32_t lo = ((uint32_t)*reinterpret_cast<uint16_t*>(&l1) << 16) |
                   (uint32_t)*reinterpret_cast<uint16_t*>(&l0);

    uint8_t* cb = g_wimg + (size_t)chunk * CHUNK_BYTES + n * 64 + 4 * s;
    *(uint32_t*)cb           = hi;
    *(uint32_t*)(cb + 16384) = lo;
}

// ---------------------------------------------------------------------------
// Encoder: 3 fused layers per 128-row tile. bf16 HMMA, ldmatrix, 4-slot cp.async
// ring with one barrier per chunk. MMA order: all-hi then all-lo per q-pair so
// same-accumulator reuse distance is 16 MMAs (hides HMMA latency).
// ---------------------------------------------------------------------------
__global__ void __launch_bounds__(THREADS, 1)
encoder_kernel(const float* __restrict__ x,
               const float* __restrict__ b1, const float* __restrict__ b2,
               const float* __restrict__ b3)
{
    extern __shared__ char smem[];
    const uint32_t sb = smem_u32(smem);
    const int tid  = threadIdx.x;
    const int lane = tid & 31;
    const int wid  = tid >> 5;
    const int wm   = wid >> 2;          // 0..1  (row half, 64 rows)
    const int wn   = wid & 3;           // 0..3  (col quarter, 64 cols)
    float* bias_s = (float*)(smem + SMEM_BIAS);
    float* red    = (float*)(smem + SMEM_RED);

    // --- prologue: prefetch weight chunks 0,1,2 (overlaps x staging) ---
#pragma unroll
    for (int c0 = 0; c0 < 3; c0++) {
        const uint8_t* src = g_wimg + (size_t)c0 * CHUNK_BYTES;
        uint32_t dst = sb + SMEM_W + (uint32_t)c0 * CHUNK_BYTES;
#pragma unroll
        for (int i = 0; i < 8; i++)
            CP16(dst + (tid + i * 256) * 16, src + (tid + i * 256) * 16);
        CP_COMMIT();
    }

    // --- stage x tile [128 x 128] fp32 -> bf16 into swizzled A (512B rows) ---
    {
        const float4* xt = (const float4*)(x + (size_t)blockIdx.x * TM * NIN);
#pragma unroll
        for (int i = tid; i < TM * NIN / 4; i += THREADS) {
            float4 v = xt[i];
            int p = i * 4;
            int r = p >> 7, cc = p & 127;
            uint32_t off = ((uint32_t)(r * 512 + cc * 2)) ^ ((uint32_t)(r & 7) << 4);
            __nv_bfloat162 lo2 = __floats2bfloat162_rn(v.x, v.y);
            __nv_bfloat162 hi2 = __floats2bfloat162_rn(v.z, v.w);
            uint2 u;
            u.x = *reinterpret_cast<uint32_t*>(&lo2);
            u.y = *reinterpret_cast<uint32_t*>(&hi2);
            *(uint2*)(smem + SMEM_A + off) = u;
        }
    }

    // --- per-thread ldmatrix address precompute ---
    uint32_t a_base[4], a_xm[4];
    {
        int r0 = wm * 64 + (lane & 15);
#pragma unroll
        for (int mt = 0; mt < 4; mt++) {
            int r = r0 + mt * 16;
            a_base[mt] = sb + SMEM_A + (uint32_t)(r * 512);
            a_xm[mt]   = ((uint32_t)(r & 7)) << 4;
        }
    }
    const uint32_t a_h16 = (uint32_t)(lane >> 4) * 16;
    uint32_t b_off[4], b_xm[4];
    {
        int n0 = wn * 64 + (lane & 7) + ((lane >> 4) << 3);
#pragma unroll
        for (int q = 0; q < 4; q++) {
            int n = n0 + q * 16;
            b_off[q] = (uint32_t)(n * 64);
            b_xm[q]  = bmask(n);
        }
    }
    const uint32_t b_h16 = ((uint32_t)(lane >> 3) & 1) * 16;

    const float* biases[3] = { b1, b2, b3 };
    const int    ncs[3]    = { 4, 8, 8 };
    const int    gg = lane >> 2, t = lane & 3;

    __syncthreads();                     // x staging done before first mma

    int g = 0;   // global chunk index (image contiguous across layers)
    for (int L = 0; L < 3; L++) {
        bias_s[tid] = biases[L][tid];

        float c[4][8][4];
#pragma unroll
        for (int mt = 0; mt < 4; mt++)
#pragma unroll
            for (int nt = 0; nt < 8; nt++)
#pragma unroll
                for (int e = 0; e < 4; e++) c[mt][nt][e] = 0.f;

        const int nc = ncs[L];
        for (int lk = 0; lk < nc; lk++, g++) {
            CP_WAIT2();                  // chunk g resident (pending: g+1, g+2)
            __syncthreads();             // all warps past chunk g-1 reads; slot (g+3)&3 free

            if (g + 3 < NCHUNKS) {       // refill slot read two chunks ago
                uint32_t dst = sb + SMEM_W + (uint32_t)((g + 3) & 3) * CHUNK_BYTES;
                const uint8_t* src = g_wimg + (size_t)(g + 3) * CHUNK_BYTES;
#pragma unroll
                for (int i = 0; i < 8; i++)
                    CP16(dst + (tid + i * 256) * 16, src + (tid + i * 256) * 16);
            }
            CP_COMMIT();                 // always commit (exact wait_group bookkeeping)

            const uint32_t wslot = sb + SMEM_W + (uint32_t)(g & 3) * CHUNK_BYTES;
#pragma unroll
            for (int ks = 0; ks < 2; ks++) {
                uint32_t a[4][4];
                const uint32_t kkA = (uint32_t)(lk * 64 + ks * 32) + a_h16;
#pragma unroll
                for (int mt = 0; mt < 4; mt++)
                    ldsm4(a[mt], a_base[mt] + (kkA ^ a_xm[mt]));

                const uint32_t kkB = (uint32_t)(ks * 32) + b_h16;
#pragma unroll
                for (int half = 0; half < 2; half++) {
                    uint32_t bh[2][4], bl[2][4];
#pragma unroll
                    for (int i = 0; i < 2; i++) {
                        const int q = half * 2 + i;
                        ldsm4(bh[i], wslot + b_off[q] + (kkB ^ b_xm[q]));
                        ldsm4(bl[i], wslot + 16384 + b_off[q] + (kkB ^ b_xm[q]));
                    }
                    // 16 hi MMAs (distinct accumulators)
#pragma unroll
                    for (int i = 0; i < 2; i++) {
                        const int nt0 = half * 4 + i * 2;
#pragma unroll
                        for (int mt = 0; mt < 4; mt++)
                            mma16(c[mt][nt0], a[mt], bh[i][0], bh[i][1]);
#pragma unroll
                        for (int mt = 0; mt < 4; mt++)
                            mma16(c[mt][nt0 + 1], a[mt], bh[i][2], bh[i][3]);
                    }
                    // 16 lo MMAs (same accumulators, 16-MMA reuse distance)
#pragma unroll
                    for (int i = 0; i < 2; i++) {
                        const int nt0 = half * 4 + i * 2;
#pragma unroll
                        for (int mt = 0; mt < 4; mt++)
                            mma16(c[mt][nt0], a[mt], bl[i][0], bl[i][1]);
#pragma unroll
                        for (int mt = 0; mt < 4; mt++)
                            mma16(c[mt][nt0 + 1], a[mt], bl[i][2], bl[i][3]);
                    }
                }
            }
        }

        __syncthreads();                 // all mma reads of A done before epilogue writes

        if (L < 2) {
            // epilogue: bias + relu -> bf16, rewrite A in place
#pragma unroll
            for (int mt = 0; mt < 4; mt++) {
                const int r0 = wm * 64 + mt * 16 + gg;
                const int r1 = r0 + 8;
                const uint32_t x0 = ((uint32_t)(r0 & 7)) << 4;
                const uint32_t x1 = ((uint32_t)(r1 & 7)) << 4;
#pragma unroll
                for (int nt = 0; nt < 8; nt++) {
                    const int col = wn * 64 + nt * 8 + 2 * t;
                    const float bb0 = bias_s[col], bb1 = bias_s[col + 1];
                    __nv_bfloat162 p0 = __floats2bfloat162_rn(
                        fmaxf(c[mt][nt][0] + bb0, 0.f), fmaxf(c[mt][nt][1] + bb1, 0.f));
                    __nv_bfloat162 p1 = __floats2bfloat162_rn(
                        fmaxf(c[mt][nt][2] + bb0, 0.f), fmaxf(c[mt][nt][3] + bb1, 0.f));
                    uint32_t o0 = ((uint32_t)(r0 * 512 + col * 2)) ^ x0;
                    uint32_t o1 = ((uint32_t)(r1 * 512 + col * 2)) ^ x1;
                    *(uint32_t*)(smem + SMEM_A + o0) = *reinterpret_cast<uint32_t*>(&p0);
                    *(uint32_t*)(smem + SMEM_A + o1) = *reinterpret_cast<uint32_t*>(&p1);
                }
            }
            __syncthreads();             // epilogue done before next bias write / mma
        } else {
            // final: bias + relu + column sums over this CTA's 128 rows
#pragma unroll
            for (int nt = 0; nt < 8; nt++) {
                const int col = wn * 64 + nt * 8 + 2 * t;
                const float bb0 = bias_s[col], bb1 = bias_s[col + 1];
                float s0 = 0.f, s1 = 0.f;
#pragma unroll
                for (int mt = 0; mt < 4; mt++) {
                    s0 += fmaxf(c[mt][nt][0] + bb0, 0.f) + fmaxf(c[mt][nt][2] + bb0, 0.f);
                    s1 += fmaxf(c[mt][nt][1] + bb1, 0.f) + fmaxf(c[mt][nt][3] + bb1, 0.f);
                }
#pragma unroll
                for (int off = 16; off >= 4; off >>= 1) {
                    s0 += __shfl_down_sync(0xffffffffu, s0, off);
                    s1 += __shfl_down_sync(0xffffffffu, s1, off);
                }
                if (lane < 4) {          // lane == t; holds this warp's 64-row sums
                    red[wm * 256 + col]     = s0;
                    red[wm * 256 + col + 1] = s1;
                }
            }
            __syncthreads();
            g_partial[(size_t)blockIdx.x * NHID + tid] = red[tid] + red[256 + tid];
        }
    }
}

// ---------------------------------------------------------------------------
// Fused decoder: mean->square->d1->d2->d3, one CTA per batch, 512 threads.
// All weight streams k-outer, coalesced row-major. Exact fp32.
// ---------------------------------------------------------------------------
__global__ void __launch_bounds__(512, 1)
decoder_kernel(const float* __restrict__ D1, const float* __restrict__ c1,
               const float* __restrict__ D2, const float* __restrict__ c2,
               const float* __restrict__ D3, const float* __restrict__ c3,
               float* __restrict__ out)
{
    __shared__ float p_s[NHID];
    __shared__ float d1_s[NDEC];
    __shared__ float d2_s[NDEC];
    __shared__ float wred[16 * NOUT];
    const int b = blockIdx.x, tid = threadIdx.x;
    const int lane = tid & 31, wrp = tid >> 5;

    // mean over 32 tile-partials (deterministic fixed order), then p = relu(m*m)
    if (tid < NHID) {
        const int tiles = NSET / TM;     // 32
        float s = 0.f;
        const float* base = g_partial + (size_t)(b * tiles) * NHID + tid;
#pragma unroll 8
        for (int i = 0; i < tiles; i++) s += base[(size_t)i * NHID];
        const float m = s * (1.0f / NSET);
        p_s[tid] = fmaxf(m * m, 0.f);
    }
    __syncthreads();

    // d1 = relu(p @ D1 + c1): thread j owns output j; k-outer coalesced stream
    {
        float acc = 0.f;
        const float* w = D1 + tid;
#pragma unroll 8
        for (int k = 0; k < NHID; k++) acc += p_s[k] * w[(size_t)k * NDEC];
        d1_s[tid] = fmaxf(acc + c1[tid], 0.f);
    }
    __syncthreads();

    // d2 = relu(d1 @ D2 + c2)
    {
        float acc = 0.f;
        const float* w = D2 + tid;
#pragma unroll 8
        for (int k = 0; k < NDEC; k++) acc += d1_s[k] * w[(size_t)k * NDEC];
        d2_s[tid] = fmaxf(acc + c2[tid], 0.f);
    }
    __syncthreads();

    // d3: thread k contributes d2[k]*D3[k][:]; warp-shfl + smem tree reduce
    {
        float part[NOUT];
        const float v = d2_s[tid];
        const float* w = D3 + (size_t)tid * NOUT;
#pragma unroll
        for (int o = 0; o < NOUT; o++) part[o] = v * w[o];
#pragma unroll
        for (int off = 16; off >= 1; off >>= 1)
#pragma unroll
            for (int o = 0; o < NOUT; o++)
                part[o] += __shfl_down_sync(0xffffffffu, part[o], off);
        if (lane == 0)
#pragma unroll
            for (int o = 0; o < NOUT; o++) wred[wrp * NOUT + o] = part[o];
    }
    __syncthreads();
    if (tid < NOUT) {
        float s = 0.f;
#pragma unroll
        for (int w = 0; w < 16; w++) s += wred[w * NOUT + tid];
        out[b * NOUT + tid] = c3[tid] + s;
    }
}

// ---------------------------------------------------------------------------
extern "C" void kernel_launch(void* const* d_in, const int* in_sizes, int n_in,
                              void* d_out, int out_size)
{
    (void)in_sizes; (void)n_in; (void)out_size;
    const float* x  = (const float*)d_in[0];
    const float* W1 = (const float*)d_in[1];
    const float* b1 = (const float*)d_in[2];
    const float* W2 = (const float*)d_in[3];
    const float* b2 = (const float*)d_in[4];
    const float* W3 = (const float*)d_in[5];
    const float* b3 = (const float*)d_in[6];
    const float* D1 = (const float*)d_in[7];
    const float* c1 = (const float*)d_in[8];
    const float* D2 = (const float*)d_in[9];
    const float* c2 = (const float*)d_in[10];
    const float* D3 = (const float*)d_in[11];
    const float* c3 = (const float*)d_in[12];

    cudaFuncSetAttribute(encoder_kernel, cudaFuncAttributeMaxDynamicSharedMemorySize, SMEM_TOTAL);

    convert_weights<<<320, 256>>>(W1, W2, W3);
    encoder_kernel<<<NTILES, THREADS, SMEM_TOTAL>>>(x, b1, b2, b3);
    decoder_kernel<<<BATCH, 512>>>(D1, c1, D2, c2, D3, c3, (float*)d_out);
}

// round 8
// speedup vs baseline: 3.0110x; 1.0175x over previous
#include <cuda_runtime.h>
#include <cuda_bf16.h>
#include <cstdint>

// ---------------------------------------------------------------------------
// Problem dims
// ---------------------------------------------------------------------------
#define NIN   128
#define NHID  256
#define NDEC  512
#define NOUT  10
#define BATCH 32
#define NSET  4096

#define TM       64                     // rows per tile
#define NTILES   (BATCH * NSET / TM)    // 2048
#define THREADS  256                    // 8 warps: 2 (row halves of 32) x 4 (col quarters)
#define GRID_ENC 296                    // persistent: 2 CTAs per SM on 148 SMs

// Weight image: k-chunks of 32, each chunk = hi(16KB) + lo(16KB) = 32KB, pre-swizzled
#define CHUNK_BYTES 32768
#define NCHUNKS     20                  // L1:4  L2:8  L3:8  (contiguous)
#define IMG_BYTES   (NCHUNKS * CHUNK_BYTES)

// SMEM layout (bytes) — total 101376 (< 113KB => 2 CTAs/SM)
#define SMEM_A     0                    // 64 rows x 512B (256 bf16), XOR-swizzled
#define SMEM_W     32768                // 2 slots x 32KB ring
#define SMEM_BIAS  98304                // 256 floats
#define SMEM_RED   99328                // 2 x 256 floats
#define SMEM_TOTAL 101376

// ---------------------------------------------------------------------------
// Device globals (static; fully rewritten every launch)
// ---------------------------------------------------------------------------
__device__ __align__(128) uint8_t g_wimg[IMG_BYTES];
__device__ float g_partial[NTILES * NHID];

// ---------------------------------------------------------------------------
// PTX helpers (baseline sm_80-era PTX only: safe at compute_103 target)
// ---------------------------------------------------------------------------
__device__ __forceinline__ uint32_t smem_u32(const void* p) {
    uint32_t a;
    asm("{ .reg .u64 t; cvta.to.shared.u64 t, %1; cvt.u32.u64 %0, t; }" : "=r"(a) : "l"(p));
    return a;
}

__device__ __forceinline__ void ldsm4(uint32_t r[4], uint32_t addr) {
    asm volatile("ldmatrix.sync.aligned.m8n8.x4.shared.b16 {%0,%1,%2,%3}, [%4];"
        : "=r"(r[0]), "=r"(r[1]), "=r"(r[2]), "=r"(r[3]) : "r"(addr));
}

__device__ __forceinline__ void mma16(float c[4], const uint32_t a[4], uint32_t b0, uint32_t b1) {
    asm volatile(
        "mma.sync.aligned.m16n8k16.row.col.f32.bf16.bf16.f32 "
        "{%0,%1,%2,%3},{%4,%5,%6,%7},{%8,%9},{%0,%1,%2,%3};"
        : "+f"(c[0]), "+f"(c[1]), "+f"(c[2]), "+f"(c[3])
        : "r"(a[0]), "r"(a[1]), "r"(a[2]), "r"(a[3]), "r"(b0), "r"(b1));
}

#define CP16(dst, src) \
    asm volatile("cp.async.cg.shared.global [%0], [%1], 16;" :: "r"(dst), "l"(src))
#define CP_COMMIT() asm volatile("cp.async.commit_group;" ::: "memory")
#define CP_WAIT1()  asm volatile("cp.async.wait_group 1;"  ::: "memory")

// B-image swizzle: rows are 64B (32 bf16 k-values); mask stays below the row
// stride (bits 4-5 only), applied to the k-offset on both store and load.
__device__ __forceinline__ uint32_t bmask(int n) { return ((uint32_t)(n >> 1) & 3u) << 4; }

// ---------------------------------------------------------------------------
// Weight pre-convert (once per launch): fp32 W[K,256] -> swizzled bf16 hi/lo image.
// One thread per packed uint32 slot; stores fully coalesced.
// ---------------------------------------------------------------------------
__global__ void __launch_bounds__(256)
convert_weights(const float* __restrict__ W1, const float* __restrict__ W2,
                const float* __restrict__ W3)
{
    int idx = blockIdx.x * 256 + threadIdx.x;    // 0 .. 81919 (uint32 slots)
    int chunk = idx >> 12;                       // 4096 slots per chunk
    int rem   = idx & 4095;
    int n     = rem >> 4;                        // 0..255
    int s     = rem & 15;                        // uint32 slot within 64B row

    const float* W; int kbase;
    if (chunk < 4)       { W = W1; kbase = chunk * 32; }
    else if (chunk < 12) { W = W2; kbase = (chunk - 4) * 32; }
    else                 { W = W3; kbase = (chunk - 12) * 32; }

    // inverse swizzle: stored byte = (k*2) ^ bm  =>  k*2 = (4s) ^ bm
    uint32_t bm = bmask(n);
    int k0 = (int)((((uint32_t)(4 * s)) ^ bm) >> 1);   // even; pair is (k0, k0+1)
    float w0 = W[(kbase + k0) * 256 + n];
    float w1 = W[(kbase + k0 + 1) * 256 + n];

    __nv_bfloat16 h0 = __float2bfloat16(w0);
    __nv_bfloat16 h1 = __float2bfloat16(w1);
    __nv_bfloat16 l0 = __float2bfloat16(w0 - __bfloat162float(h0));
    __nv_bfloat16 l1 = __float2bfloat16(w1 - __bfloat162float(h1));

    uint32_t hi = ((uint32_t)*reinterpret_cast<uint16_t*>(&h1) << 16) |
                   (uint32_t)*reinterpret_cast<uint16_t*>(&h0);
    uint32_t lo = ((uint32_t)*reinterpret_cast<uint16_t*>(&l1) << 16) |
                   (uint32_t)*reinterpret_cast<uint16_t*>(&l0);

    uint8_t* cb = g_wimg + (size_t)chunk * CHUNK_BYTES + n * 64 + 4 * s;
    *(uint32_t*)cb           = hi;
    *(uint32_t*)(cb + 16384) = lo;
}

// ---------------------------------------------------------------------------
// Encoder: persistent, 2 CTAs/SM, TM=64 tiles, 3 fused layers per tile.
// Weight chunk stream is periodic (period 20, even) so the 2-slot ring's
// parity is seamless across tiles.
// ---------------------------------------------------------------------------
__global__ void __launch_bounds__(THREADS, 2)
encoder_kernel(const float* __restrict__ x,
               const float* __restrict__ b1, const float* __restrict__ b2,
               const float* __restrict__ b3)
{
    extern __shared__ char smem[];
    const uint32_t sb = smem_u32(smem);
    const int tid  = threadIdx.x;
    const int lane = tid & 31;
    const int wid  = tid >> 5;
    const int wm   = wid >> 2;          // 0..1  (row half, 32 rows)
    const int wn   = wid & 3;           // 0..3  (col quarter, 64 cols)
    float* bias_s = (float*)(smem + SMEM_BIAS);
    float* red    = (float*)(smem + SMEM_RED);

    // --- prologue: prefetch weight chunks 0,1 (once; ring refills keep flowing) ---
#pragma unroll
    for (int c0 = 0; c0 < 2; c0++) {
        const uint8_t* src = g_wimg + (size_t)c0 * CHUNK_BYTES;
        uint32_t dst = sb + SMEM_W + (uint32_t)c0 * CHUNK_BYTES;
#pragma unroll
        for (int i = 0; i < 8; i++)
            CP16(dst + (tid + i * 256) * 16, src + (tid + i * 256) * 16);
        CP_COMMIT();
    }

    // --- per-thread ldmatrix address precompute ---
    uint32_t a_base[2], a_xm[2];
    {
        int r0 = wm * 32 + (lane & 15);
#pragma unroll
        for (int mt = 0; mt < 2; mt++) {
            int r = r0 + mt * 16;
            a_base[mt] = sb + SMEM_A + (uint32_t)(r * 512);
            a_xm[mt]   = ((uint32_t)(r & 7)) << 4;
        }
    }
    const uint32_t a_h16 = (uint32_t)(lane >> 4) * 16;
    uint32_t b_off[4], b_xm[4];
    {
        int n0 = wn * 64 + (lane & 7) + ((lane >> 4) << 3);
#pragma unroll
        for (int q = 0; q < 4; q++) {
            int n = n0 + q * 16;
            b_off[q] = (uint32_t)(n * 64);
            b_xm[q]  = bmask(n);
        }
    }
    const uint32_t b_h16 = ((uint32_t)(lane >> 3) & 1) * 16;

    const float* biases[3] = { b1, b2, b3 };
    const int    ncs[3]    = { 4, 8, 8 };
    const int    gg = lane >> 2, t = lane & 3;

    for (int tile = blockIdx.x; tile < NTILES; tile += GRID_ENC) {
        // --- stage x tile [64 x 128] fp32 -> bf16 into swizzled A (512B rows) ---
        // (A is free here: previous tile's last MMA reads were fenced by the
        //  post-chunk-loop barrier of layer 3.)
        {
            const float4* xt = (const float4*)(x + (size_t)tile * TM * NIN);
#pragma unroll
            for (int i = tid; i < TM * NIN / 4; i += THREADS) {
                float4 v = xt[i];
                int p = i * 4;
                int r = p >> 7, cc = p & 127;
                uint32_t off = ((uint32_t)(r * 512 + cc * 2)) ^ ((uint32_t)(r & 7) << 4);
                __nv_bfloat162 lo2 = __floats2bfloat162_rn(v.x, v.y);
                __nv_bfloat162 hi2 = __floats2bfloat162_rn(v.z, v.w);
                uint2 u;
                u.x = *reinterpret_cast<uint32_t*>(&lo2);
                u.y = *reinterpret_cast<uint32_t*>(&hi2);
                *(uint2*)(smem + SMEM_A + off) = u;
            }
        }
        __syncthreads();                 // x staged before layer-1 MMAs

        int g = 0;                       // within-tile chunk index (0..19)
        for (int L = 0; L < 3; L++) {
            bias_s[tid] = biases[L][tid];

            float c[2][8][4];
#pragma unroll
            for (int mt = 0; mt < 2; mt++)
#pragma unroll
                for (int nt = 0; nt < 8; nt++)
#pragma unroll
                    for (int e = 0; e < 4; e++) c[mt][nt][e] = 0.f;

            const int nc = ncs[L];
            for (int lk = 0; lk < nc; lk++, g++) {
                CP_WAIT1();              // chunk g resident (1 pending: g+1)
                __syncthreads();

                const uint32_t wslot = sb + SMEM_W + (uint32_t)(g & 1) * CHUNK_BYTES;
#pragma unroll
                for (int ks = 0; ks < 2; ks++) {
                    uint32_t a[2][4];
                    const uint32_t kkA = (uint32_t)(lk * 64 + ks * 32) + a_h16;
#pragma unroll
                    for (int mt = 0; mt < 2; mt++)
                        ldsm4(a[mt], a_base[mt] + (kkA ^ a_xm[mt]));

                    const uint32_t kkB = (uint32_t)(ks * 32) + b_h16;
#pragma unroll
                    for (int q = 0; q < 4; q++) {
                        uint32_t bh[4], bl[4];
                        ldsm4(bh, wslot + b_off[q] + (kkB ^ b_xm[q]));
                        ldsm4(bl, wslot + 16384 + b_off[q] + (kkB ^ b_xm[q]));
                        const int nt0 = 2 * q;
#pragma unroll
                        for (int mt = 0; mt < 2; mt++) {
                            mma16(c[mt][nt0],     a[mt], bh[0], bh[1]);
                            mma16(c[mt][nt0 + 1], a[mt], bh[2], bh[3]);
                        }
#pragma unroll
                        for (int mt = 0; mt < 2; mt++) {
                            mma16(c[mt][nt0],     a[mt], bl[0], bl[1]);
                            mma16(c[mt][nt0 + 1], a[mt], bl[2], bl[3]);
                        }
                    }
                }

                __syncthreads();         // all warps done reading slot g&1
                {                        // refill it with chunk (g+2) mod 20 (periodic stream)
                    int nxt = g + 2; if (nxt >= NCHUNKS) nxt -= NCHUNKS;
                    uint32_t dst = sb + SMEM_W + (uint32_t)(g & 1) * CHUNK_BYTES;
                    const uint8_t* src = g_wimg + (size_t)nxt * CHUNK_BYTES;
#pragma unroll
                    for (int i = 0; i < 8; i++)
                        CP16(dst + (tid + i * 256) * 16, src + (tid + i * 256) * 16);
                }
                CP_COMMIT();
            }

            if (L < 2) {
                // epilogue: bias + relu -> bf16, rewrite A in place
#pragma unroll
                for (int mt = 0; mt < 2; mt++) {
                    const int r0 = wm * 32 + mt * 16 + gg;
                    const int r1 = r0 + 8;
                    const uint32_t x0 = ((uint32_t)(r0 & 7)) << 4;
                    const uint32_t x1 = ((uint32_t)(r1 & 7)) << 4;
#pragma unroll
                    for (int nt = 0; nt < 8; nt++) {
                        const int col = wn * 64 + nt * 8 + 2 * t;
                        const float bb0 = bias_s[col], bb1 = bias_s[col + 1];
                        __nv_bfloat162 p0 = __floats2bfloat162_rn(
                            fmaxf(c[mt][nt][0] + bb0, 0.f), fmaxf(c[mt][nt][1] + bb1, 0.f));
                        __nv_bfloat162 p1 = __floats2bfloat162_rn(
                            fmaxf(c[mt][nt][2] + bb0, 0.f), fmaxf(c[mt][nt][3] + bb1, 0.f));
                        uint32_t o0 = ((uint32_t)(r0 * 512 + col * 2)) ^ x0;
                        uint32_t o1 = ((uint32_t)(r1 * 512 + col * 2)) ^ x1;
                        *(uint32_t*)(smem + SMEM_A + o0) = *reinterpret_cast<uint32_t*>(&p0);
                        *(uint32_t*)(smem + SMEM_A + o1) = *reinterpret_cast<uint32_t*>(&p1);
                    }
                }
                __syncthreads();         // epilogue done before next layer's reads
            } else {
                // final: bias + relu + column sums over this warp's 32 rows
#pragma unroll
                for (int nt = 0; nt < 8; nt++) {
                    const int col = wn * 64 + nt * 8 + 2 * t;
                    const float bb0 = bias_s[col], bb1 = bias_s[col + 1];
                    float s0 = 0.f, s1 = 0.f;
#pragma unroll
                    for (int mt = 0; mt < 2; mt++) {
                        s0 += fmaxf(c[mt][nt][0] + bb0, 0.f) + fmaxf(c[mt][nt][2] + bb0, 0.f);
                        s1 += fmaxf(c[mt][nt][1] + bb1, 0.f) + fmaxf(c[mt][nt][3] + bb1, 0.f);
                    }
#pragma unroll
                    for (int off = 16; off >= 4; off >>= 1) {
                        s0 += __shfl_down_sync(0xffffffffu, s0, off);
                        s1 += __shfl_down_sync(0xffffffffu, s1, off);
                    }
                    if (lane < 4) {      // lane == t; full 32-row sums for this warp
                        red[wm * 256 + col]     = s0;
                        red[wm * 256 + col + 1] = s1;
                    }
                }
                __syncthreads();
                g_partial[(size_t)tile * NHID + tid] = red[tid] + red[256 + tid];
                __syncthreads();         // red consumed before next tile reuses it
            }
        }
    }
}

// ---------------------------------------------------------------------------
// Fused decoder: mean->square->d1->d2->d3, one CTA per batch, 512 threads.
// All weight streams k-outer, coalesced row-major. Exact fp32.
// ---------------------------------------------------------------------------
__global__ void __launch_bounds__(512, 1)
decoder_kernel(const float* __restrict__ D1, const float* __restrict__ c1,
               const float* __restrict__ D2, const float* __restrict__ c2,
               const float* __restrict__ D3, const float* __restrict__ c3,
               float* __restrict__ out)
{
    __shared__ float p_s[NHID];
    __shared__ float d1_s[NDEC];
    __shared__ float d2_s[NDEC];
    __shared__ float wred[16 * NOUT];
    const int b = blockIdx.x, tid = threadIdx.x;
    const int lane = tid & 31, wrp = tid >> 5;

    // mean over 64 tile-partials (deterministic fixed order), then p = relu(m*m)
    if (tid < NHID) {
        const int tiles = NSET / TM;     // 64
        float s = 0.f;
        const float* base = g_partial + (size_t)(b * tiles) * NHID + tid;
#pragma unroll 8
        for (int i = 0; i < tiles; i++) s += base[(size_t)i * NHID];
        const float m = s * (1.0f / NSET);
        p_s[tid] = fmaxf(m * m, 0.f);
    }
    __syncthreads();

    // d1 = relu(p @ D1 + c1): thread j owns output j; k-outer coalesced stream
    {
        float acc = 0.f;
        const float* w = D1 + tid;
#pragma unroll 8
        for (int k = 0; k < NHID; k++) acc += p_s[k] * w[(size_t)k * NDEC];
        d1_s[tid] = fmaxf(acc + c1[tid], 0.f);
    }
    __syncthreads();

    // d2 = relu(d1 @ D2 + c2)
    {
        float acc = 0.f;
        const float* w = D2 + tid;
#pragma unroll 8
        for (int k = 0; k < NDEC; k++) acc += d1_s[k] * w[(size_t)k * NDEC];
        d2_s[tid] = fmaxf(acc + c2[tid], 0.f);
    }
    __syncthreads();

    // d3: thread k contributes d2[k]*D3[k][:]; warp-shfl + smem tree reduce
    {
        float part[NOUT];
        const float v = d2_s[tid];
        const float* w = D3 + (size_t)tid * NOUT;
#pragma unroll
        for (int o = 0; o < NOUT; o++) part[o] = v * w[o];
#pragma unroll
        for (int off = 16; off >= 1; off >>= 1)
#pragma unroll
            for (int o = 0; o < NOUT; o++)
                part[o] += __shfl_down_sync(0xffffffffu, part[o], off);
        if (lane == 0)
#pragma unroll
            for (int o = 0; o < NOUT; o++) wred[wrp * NOUT + o] = part[o];
    }
    __syncthreads();
    if (tid < NOUT) {
        float s = 0.f;
#pragma unroll
        for (int w = 0; w < 16; w++) s += wred[w * NOUT + tid];
        out[b * NOUT + tid] = c3[tid] + s;
    }
}

// ---------------------------------------------------------------------------
extern "C" void kernel_launch(void* const* d_in, const int* in_sizes, int n_in,
                              void* d_out, int out_size)
{
    (void)in_sizes; (void)n_in; (void)out_size;
    const float* x  = (const float*)d_in[0];
    const float* W1 = (const float*)d_in[1];
    const float* b1 = (const float*)d_in[2];
    const float* W2 = (const float*)d_in[3];
    const float* b2 = (const float*)d_in[4];
    const float* W3 = (const float*)d_in[5];
    const float* b3 = (const float*)d_in[6];
    const float* D1 = (const float*)d_in[7];
    const float* c1 = (const float*)d_in[8];
    const float* D2 = (const float*)d_in[9];
    const float* c2 = (const float*)d_in[10];
    const float* D3 = (const float*)d_in[11];
    const float* c3 = (const float*)d_in[12];

    cudaFuncSetAttribute(encoder_kernel, cudaFuncAttributeMaxDynamicSharedMemorySize, SMEM_TOTAL);

    convert_weights<<<320, 256>>>(W1, W2, W3);
    encoder_kernel<<<GRID_ENC, THREADS, SMEM_TOTAL>>>(x, b1, b2, b3);
    decoder_kernel<<<BATCH, 512>>>(D1, c1, D2, c2, D3, c3, (float*)d_out);
}